// round 13
// baseline (speedup 1.0000x reference)
#include <cuda_runtime.h>
#include <cuda_fp16.h>
#include <math.h>
#include <stdint.h>

// ---------------------------------------------------------------------------
// AIO_DownsampleCouplingBlock — Round 13: 64x64 warp tiles (4-warp CTAs,
// 255 regs). Halves A-fragment smem duplication; deep register ILP.
// ---------------------------------------------------------------------------

__device__ __align__(16) __half g_xh[32 * 64 * 64 * 48];    // x1 NHWC half
__device__ __align__(16) __half g_y2h[32 * 32 * 32 * 192];  // y2 NHWC half
__device__ __align__(16) __half g_wp1[9 * 384 * 48];        // conv1 w [tap][nn][48]
__device__ __align__(16) __half g_wp2[27 * 384 * 64];       // conv2 w [st][nn][64]
__device__ int   g_invperm[384];
__device__ float g_scale[384];

__device__ __forceinline__ void cp_async16(unsigned dst, const void* src) {
    asm volatile("cp.async.cg.shared.global [%0], [%1], 16;\n"
                 :: "r"(dst), "l"(src));
}
__device__ __forceinline__ void cp_async16z(unsigned dst, const void* src, int sz) {
    asm volatile("cp.async.cg.shared.global [%0], [%1], 16, %2;\n"
                 :: "r"(dst), "l"(src), "r"(sz));
}
__device__ __forceinline__ void ldsm4(uint32_t& r0, uint32_t& r1,
                                      uint32_t& r2, uint32_t& r3, unsigned addr) {
    asm volatile("ldmatrix.sync.aligned.m8n8.x4.shared.b16 {%0,%1,%2,%3}, [%4];"
                 : "=r"(r0), "=r"(r1), "=r"(r2), "=r"(r3) : "r"(addr));
}

// ---------------------------------------------------------------------------
__global__ void prep_kernel(const float* __restrict__ perm_w,
                            const float* __restrict__ act_norm) {
    int p = threadIdx.x;
    if (p < 384) {
        int o_found = 0;
        for (int o = 0; o < 384; ++o)
            if (perm_w[o * 384 + p] > 0.5f) o_found = o;
        g_invperm[p] = o_found;
        g_scale[p] = 0.2f * log1pf(expf(0.5f * act_norm[p]));
    }
}

// nn remap (128-col N-blocks): block y = nn>>7, r = nn&127:
//   r < 64 : n = y*64 + r ; r >= 64 : n = 192 + y*64 + (r-64)
__device__ __forceinline__ int nn_to_n(int nn) {
    int yb = nn >> 7, r = nn & 127;
    return (r < 64) ? (yb * 64 + r) : (192 + yb * 64 + (r - 64));
}

// both weight packs: dst[st][nn(384)][k(KB)], exact K (no pad)
__global__ void pack_all_kernel(const float* __restrict__ w_hi,
                                const float* __restrict__ w_lo) {
    const int T1 = 9 * 384 * 48;
    const int T2 = 27 * 384 * 64;
    int idx = blockIdx.x * 256 + threadIdx.x;
    if (idx < T1) {
        int k = idx % 48;
        int nn = (idx / 48) % 384;
        int tap = idx / (48 * 384);
        int n = nn_to_n(nn);
        g_wp1[idx] = __float2half(w_hi[(n * 48 + k) * 9 + tap]);
    } else if (idx < T1 + T2) {
        int j = idx - T1;
        int k = j % 64;
        int nn = (j / 64) % 384;
        int st = j / (64 * 384);          // tap = st/3, cblk = st%3
        int n = nn_to_n(nn);
        int tap = st / 3;
        int c = (st % 3) * 64 + k;
        g_wp2[j] = __float2half(w_lo[(n * 192 + c) * 9 + tap]);
    }
}

// x (NCHW f32, first 48 channels) -> g_xh (NHWC half), half2 stores
__global__ __launch_bounds__(256) void x2h_kernel(const float* __restrict__ x) {
    __shared__ float tile[48][65];
    const int b = blockIdx.x >> 6, h = blockIdx.x & 63;
    for (int idx = threadIdx.x; idx < 48 * 64; idx += 256) {
        const int c = idx >> 6, w = idx & 63;
        tile[c][w] = x[(((size_t)b * 96 + c) * 64 + h) * 64 + w];
    }
    __syncthreads();
    for (int idx = threadIdx.x; idx < 64 * 24; idx += 256) {
        const int w = idx / 24, cp = idx % 24;
        __half2 v = __floats2half2_rn(tile[2 * cp][w], tile[2 * cp + 1][w]);
        *(__half2*)&g_xh[(((size_t)b * 64 + h) * 64 + w) * 48 + 2 * cp] = v;
    }
}

// ---------------------------------------------------------------------------
// fused implicit-GEMM conv + affine epilogue.
// 128 threads / 4 warps (255 regs), warp grid 2(M) x 2(N), warp tile 64x64.
// BM=128, BN=128 (64 lo + 64 paired hi). A/B smem rows padded +16B.
// Loaders: thread = row, chunk loop (no divisions).
// ---------------------------------------------------------------------------
template <int KB, int NST, int CH, int STRIDE, int HIN, int CTOT, int WHICH>
__global__ __launch_bounds__(128, 2) void conv_fused(
    const float* __restrict__ x,
    const float* __restrict__ bias,
    const float* __restrict__ act_offset,
    float* __restrict__ outp) {
    extern __shared__ __align__(16) char smem[];

    constexpr int ROWB   = KB * 2 + 16;      // bytes per smem row
    constexpr int ASTG   = 128 * ROWB;
    constexpr int STGB   = 2 * ASTG;         // A + B (128 rows each)
    constexpr int KSTEPS = KB / 16;
    constexpr int CHK    = KB / 8;           // 16B chunks per row
    constexpr int NIT    = 9 * CH;

    const __half* inp = (WHICH == 1) ? (const __half*)g_xh : (const __half*)g_y2h;
    const __half* wp  = (WHICH == 1) ? (const __half*)g_wp1 : (const __half*)g_wp2;
    constexpr int XOFF  = (WHICH == 1) ? 48 : 0;
    constexpr int PBASE = (WHICH == 1) ? 192 : 0;

    const int tid  = threadIdx.x;
    const int lane = tid & 31;
    const int warp = tid >> 5;
    const int wm = warp >> 1;                // 0..1
    const int wn = warp & 1;                 // 0..1
    const int g4 = lane >> 2;
    const int t4 = lane & 3;

    const int bm   = blockIdx.x;
    const int bimg = bm >> 3;
    const int h0   = (bm & 7) * 4;
    const int yb   = blockIdx.y;             // 0..2
    const int n0   = yb * 128;

    const unsigned smemBase = (unsigned)__cvta_generic_to_shared(smem);
    const int aRowL = wm * 64 + (lane & 15);
    const int aKoffL = (lane >> 4) << 4;
    const int bRowL = wn * 32 + ((lane >> 4) << 3) + (lane & 7);
    const int bKoffL = ((lane >> 3) & 1) << 4;

    // A-loader geometry for this thread (row = tid), precomputed
    const int arow_h = h0 + (tid >> 5);
    const int arow_w = tid & 31;

    float acc[4][8][4];
#pragma unroll
    for (int i = 0; i < 4; i++)
#pragma unroll
        for (int j = 0; j < 8; j++)
#pragma unroll
            for (int k = 0; k < 4; k++) acc[i][j][k] = 0.f;

    auto load_stage = [&](int it, int s) {
        const int tap = it / CH;
        const int c0  = (it - tap * CH) * KB;
        const int dh = tap / 3 - 1;
        const int dw = tap % 3 - 1;
        const unsigned aB = smemBase + s * STGB;
        const unsigned bB = aB + ASTG;
        // A: thread = pixel row; CHK contiguous 16B chunks
        {
            const int ih = arow_h * STRIDE + dh;
            const int iw = arow_w * STRIDE + dw;
            const bool ok = (ih >= 0) && (ih < HIN) && (iw >= 0) && (iw < HIN);
            const __half* src = ok
                ? inp + ((size_t)(bimg * HIN + ih) * HIN + iw) * CTOT + c0
                : inp;
            const unsigned dst = aB + (unsigned)(tid * ROWB);
            const int sz = ok ? 16 : 0;
#pragma unroll
            for (int ch = 0; ch < CHK; ++ch)
                cp_async16z(dst + ch * 16u, src + ch * 8, sz);
        }
        // B: thread = n-row; CHK contiguous 16B chunks (packed source)
        {
            const __half* src = wp + (size_t)it * (384 * KB) + (size_t)(n0 + tid) * KB;
            const unsigned dst = bB + (unsigned)(tid * ROWB);
#pragma unroll
            for (int ch = 0; ch < CHK; ++ch)
                cp_async16(dst + ch * 16u, src + ch * 8);
        }
    };

    // prologue: NST-1 stages in flight
#pragma unroll
    for (int ps = 0; ps < NST - 1; ++ps) {
        load_stage(ps, ps);
        asm volatile("cp.async.commit_group;\n" ::: "memory");
    }

    int s = 0;
#pragma unroll 1
    for (int it = 0; it < NIT; ++it) {
        int wgn = NIT - 1 - it;
        if (wgn > NST - 2) wgn = NST - 2;
        if (wgn <= 0)
            asm volatile("cp.async.wait_group 0;\n" ::: "memory");
        else if (wgn == 1)
            asm volatile("cp.async.wait_group 1;\n" ::: "memory");
        else
            asm volatile("cp.async.wait_group 2;\n" ::: "memory");
        __syncthreads();

        if (it + NST - 1 < NIT) {
            int sw = s - 1; if (sw < 0) sw += NST;   // == (it+NST-1) % NST
            load_stage(it + NST - 1, sw);
            asm volatile("cp.async.commit_group;\n" ::: "memory");
        }

        const unsigned aB = smemBase + s * STGB;
        const unsigned bB = aB + ASTG;
#pragma unroll
        for (int step = 0; step < KSTEPS; ++step) {
            const int kb = step * 32;
            uint32_t af[4][4];
#pragma unroll
            for (int mi = 0; mi < 4; ++mi)
                ldsm4(af[mi][0], af[mi][1], af[mi][2], af[mi][3],
                      aB + (unsigned)((aRowL + mi * 16) * ROWB + kb + aKoffL));
            uint32_t bf[8][2];
            ldsm4(bf[0][0], bf[0][1], bf[1][0], bf[1][1],
                  bB + (unsigned)(bRowL * ROWB + kb + bKoffL));
            ldsm4(bf[2][0], bf[2][1], bf[3][0], bf[3][1],
                  bB + (unsigned)((bRowL + 16) * ROWB + kb + bKoffL));
            ldsm4(bf[4][0], bf[4][1], bf[5][0], bf[5][1],
                  bB + (unsigned)((bRowL + 64) * ROWB + kb + bKoffL));
            ldsm4(bf[6][0], bf[6][1], bf[7][0], bf[7][1],
                  bB + (unsigned)((bRowL + 80) * ROWB + kb + bKoffL));
#pragma unroll
            for (int mi = 0; mi < 4; ++mi)
#pragma unroll
                for (int ni = 0; ni < 8; ++ni) {
                    asm volatile(
                        "mma.sync.aligned.m16n8k16.row.col.f32.f16.f16.f32 "
                        "{%0,%1,%2,%3}, {%4,%5,%6,%7}, {%8,%9}, {%0,%1,%2,%3};"
                        : "+f"(acc[mi][ni][0]), "+f"(acc[mi][ni][1]),
                          "+f"(acc[mi][ni][2]), "+f"(acc[mi][ni][3])
                        : "r"(af[mi][0]), "r"(af[mi][1]),
                          "r"(af[mi][2]), "r"(af[mi][3]),
                          "r"(bf[ni][0]), "r"(bf[ni][1]));
                }
        }
        if (++s == NST) s = 0;
    }

    // ---- fused affine epilogue -------------------------------------------
    // ni in {0..3}: lo channel c = yb*64 + wn*32 + ni*8 + 2*t4 (+0/1)
    // paired hi accumulator at ni+4 (channel c+192)
#pragma unroll
    for (int ni = 0; ni < 4; ++ni) {
        const int c = yb * 64 + wn * 32 + ni * 8 + 2 * t4;   // even
        const float bl0 = bias[c],        bl1 = bias[c + 1];
        const float bh0 = bias[c + 192],  bh1 = bias[c + 193];
        const int p0 = PBASE + c, p1 = PBASE + c + 1;
        const float sc0 = g_scale[p0], sc1 = g_scale[p1];
        const float ao0 = act_offset[p0], ao1 = act_offset[p1];
        const int o0 = g_invperm[p0], o1 = g_invperm[p1];
        const int cc = c >> 2, ii = (c >> 1) & 1;
        const float* xrowb = x + (((size_t)bimg * 96 + XOFF + cc) * 64 + ii) * 64;
#pragma unroll
        for (int mi = 0; mi < 4; ++mi) {
#pragma unroll
            for (int rr = 0; rr < 2; ++rr) {
                const int m = wm * 64 + mi * 16 + g4 + rr * 8;
                const int h = h0 + (m >> 5);
                const int w = m & 31;
                const float lo0 = acc[mi][ni][rr * 2 + 0] + bl0;
                const float lo1 = acc[mi][ni][rr * 2 + 1] + bl1;
                const float hi0 = acc[mi][ni + 4][rr * 2 + 0] + bh0;
                const float hi1 = acc[mi][ni + 4][rr * 2 + 1] + bh1;
                const float2 xd = *(const float2*)&xrowb[(size_t)(2 * h) * 64 + 2 * w];
                const float y0 = xd.x * expf(2.0f * tanhf(0.2f * lo0)) + hi0;
                const float y1 = xd.y * expf(2.0f * tanhf(0.2f * lo1)) + hi1;
                const int hw = h * 32 + w;
                if (WHICH == 1) {
                    *(__half2*)&g_y2h[(((size_t)(bimg * 32 + h) * 32) + w) * 192 + c] =
                        __floats2half2_rn(y0, y1);
                }
                outp[(((size_t)(bimg * 384 + o0)) << 10) + hw] = y0 * sc0 + ao0;
                outp[(((size_t)(bimg * 384 + o1)) << 10) + hw] = y1 * sc1 + ao1;
            }
        }
    }
}

// ---------------------------------------------------------------------------
extern "C" void kernel_launch(void* const* d_in, const int* in_sizes, int n_in,
                              void* d_out, int out_size) {
    const float* x          = (const float*)d_in[0];
    const float* w_hi       = (const float*)d_in[1];
    const float* b_hi       = (const float*)d_in[2];
    const float* w_lo       = (const float*)d_in[3];
    const float* b_lo       = (const float*)d_in[4];
    const float* act_norm   = (const float*)d_in[5];
    const float* act_offset = (const float*)d_in[6];
    const float* perm_w     = (const float*)d_in[7];
    float* out = (float*)d_out;

    // conv1: KB=48, NST=3 -> stage 28,672 B, total 86,016 B  (2 CTAs/SM)
    // conv2: KB=64, NST=3 -> stage 36,864 B, total 110,592 B (2 CTAs/SM)
    const int SMEM1 = 3 * 2 * 128 * (48 * 2 + 16);
    const int SMEM2 = 3 * 2 * 128 * (64 * 2 + 16);

    cudaFuncSetAttribute(conv_fused<48, 3, 1, 2, 64, 48, 1>,
                         cudaFuncAttributeMaxDynamicSharedMemorySize, SMEM1);
    cudaFuncSetAttribute(conv_fused<64, 3, 3, 1, 32, 192, 2>,
                         cudaFuncAttributeMaxDynamicSharedMemorySize, SMEM2);

    prep_kernel<<<1, 384>>>(perm_w, act_norm);
    {
        int total = 9 * 384 * 48 + 27 * 384 * 64;
        pack_all_kernel<<<(total + 255) / 256, 256>>>(w_hi, w_lo);
    }
    x2h_kernel<<<32 * 64, 256>>>(x);

    conv_fused<48, 3, 1, 2, 64, 48, 1><<<dim3(256, 3), 128, SMEM1>>>(
        x, b_hi, act_offset, out);

    conv_fused<64, 3, 3, 1, 32, 192, 2><<<dim3(256, 3), 128, SMEM2>>>(
        x, b_lo, act_offset, out);
}

// round 15
// speedup vs baseline: 1.3817x; 1.3817x over previous
#include <cuda_runtime.h>
#include <cuda_fp16.h>
#include <math.h>
#include <stdint.h>

// ---------------------------------------------------------------------------
// AIO_DownsampleCouplingBlock — Round 14: BM=256 (512-thread CTA, 16 warps,
// 64x32 warp tiles as in round 11). 25% fewer cp.async ops/FLOP, half the
// B-tile L2 traffic. Fused affine epilogues.
// ---------------------------------------------------------------------------

__device__ __align__(16) __half g_xh[32 * 64 * 64 * 48];    // x1 NHWC half
__device__ __align__(16) __half g_y2h[32 * 32 * 32 * 192];  // y2 NHWC half
__device__ __align__(16) __half g_wp1[9 * 384 * 48];        // conv1 w [tap][nn][48]
__device__ __align__(16) __half g_wp2[27 * 384 * 64];       // conv2 w [st][nn][64]
__device__ int   g_invperm[384];
__device__ float g_scale[384];

__device__ __forceinline__ void cp_async16(unsigned dst, const void* src) {
    asm volatile("cp.async.cg.shared.global [%0], [%1], 16;\n"
                 :: "r"(dst), "l"(src));
}
__device__ __forceinline__ void cp_async16z(unsigned dst, const void* src, int sz) {
    asm volatile("cp.async.cg.shared.global [%0], [%1], 16, %2;\n"
                 :: "r"(dst), "l"(src), "r"(sz));
}
__device__ __forceinline__ void ldsm4(uint32_t& r0, uint32_t& r1,
                                      uint32_t& r2, uint32_t& r3, unsigned addr) {
    asm volatile("ldmatrix.sync.aligned.m8n8.x4.shared.b16 {%0,%1,%2,%3}, [%4];"
                 : "=r"(r0), "=r"(r1), "=r"(r2), "=r"(r3) : "r"(addr));
}

// ---------------------------------------------------------------------------
__global__ void prep_kernel(const float* __restrict__ perm_w,
                            const float* __restrict__ act_norm) {
    int p = threadIdx.x;
    if (p < 384) {
        int o_found = 0;
        for (int o = 0; o < 384; ++o)
            if (perm_w[o * 384 + p] > 0.5f) o_found = o;
        g_invperm[p] = o_found;
        g_scale[p] = 0.2f * log1pf(expf(0.5f * act_norm[p]));
    }
}

// nn remap (128-col N-blocks): block y = nn>>7, r = nn&127:
//   r < 64 : n = y*64 + r ; r >= 64 : n = 192 + y*64 + (r-64)
__device__ __forceinline__ int nn_to_n(int nn) {
    int yb = nn >> 7, r = nn & 127;
    return (r < 64) ? (yb * 64 + r) : (192 + yb * 64 + (r - 64));
}

// both weight packs: dst[st][nn(384)][k(KB)], exact K (no pad)
__global__ void pack_all_kernel(const float* __restrict__ w_hi,
                                const float* __restrict__ w_lo) {
    const int T1 = 9 * 384 * 48;
    const int T2 = 27 * 384 * 64;
    int idx = blockIdx.x * 256 + threadIdx.x;
    if (idx < T1) {
        int k = idx % 48;
        int nn = (idx / 48) % 384;
        int tap = idx / (48 * 384);
        int n = nn_to_n(nn);
        g_wp1[idx] = __float2half(w_hi[(n * 48 + k) * 9 + tap]);
    } else if (idx < T1 + T2) {
        int j = idx - T1;
        int k = j % 64;
        int nn = (j / 64) % 384;
        int st = j / (64 * 384);          // tap = st/3, cblk = st%3
        int n = nn_to_n(nn);
        int tap = st / 3;
        int c = (st % 3) * 64 + k;
        g_wp2[j] = __float2half(w_lo[(n * 192 + c) * 9 + tap]);
    }
}

// x (NCHW f32, first 48 channels) -> g_xh (NHWC half), half2 stores
__global__ __launch_bounds__(256) void x2h_kernel(const float* __restrict__ x) {
    __shared__ float tile[48][65];
    const int b = blockIdx.x >> 6, h = blockIdx.x & 63;
    for (int idx = threadIdx.x; idx < 48 * 64; idx += 256) {
        const int c = idx >> 6, w = idx & 63;
        tile[c][w] = x[(((size_t)b * 96 + c) * 64 + h) * 64 + w];
    }
    __syncthreads();
    for (int idx = threadIdx.x; idx < 64 * 24; idx += 256) {
        const int w = idx / 24, cp = idx % 24;
        __half2 v = __floats2half2_rn(tile[2 * cp][w], tile[2 * cp + 1][w]);
        *(__half2*)&g_xh[(((size_t)b * 64 + h) * 64 + w) * 48 + 2 * cp] = v;
    }
}

// ---------------------------------------------------------------------------
// fused implicit-GEMM conv + affine epilogue.
// 512 threads / 16 warps, warp grid 4(M) x 4(N), warp tile 64x32 (round-11
// proven layout). BM=256 (8 pixel rows), BN=128 (64 lo + 64 paired hi).
// A smem [m(256)][KB halves], B smem [nn(128)][KB], rows padded +16B.
// ---------------------------------------------------------------------------
template <int KB, int NST, int CH, int STRIDE, int HIN, int CTOT, int WHICH>
__global__ __launch_bounds__(512, 1) void conv_fused(
    const float* __restrict__ x,
    const float* __restrict__ bias,
    const float* __restrict__ act_offset,
    float* __restrict__ outp) {
    extern __shared__ __align__(16) char smem[];

    constexpr int ROWB   = KB * 2 + 16;      // bytes per smem row
    constexpr int ASTG   = 256 * ROWB;
    constexpr int BSTG   = 128 * ROWB;
    constexpr int STGB   = ASTG + BSTG;
    constexpr int KSTEPS = KB / 16;
    constexpr int CHK    = KB / 8;           // 16B chunks per row
    constexpr int NIT    = 9 * CH;

    const __half* inp = (WHICH == 1) ? (const __half*)g_xh : (const __half*)g_y2h;
    const __half* wp  = (WHICH == 1) ? (const __half*)g_wp1 : (const __half*)g_wp2;
    constexpr int XOFF  = (WHICH == 1) ? 48 : 0;
    constexpr int PBASE = (WHICH == 1) ? 192 : 0;

    const int tid  = threadIdx.x;
    const int lane = tid & 31;
    const int warp = tid >> 5;
    const int wm = warp >> 2;                // 0..3 (64-row M slices)
    const int wn = warp & 3;                 // 0..3 (16 lo + 16 hi cols)
    const int g4 = lane >> 2;
    const int t4 = lane & 3;

    const int bm   = blockIdx.x;             // 0..127
    const int bimg = bm >> 2;
    const int h0   = (bm & 3) * 8;           // 8 output rows per block
    const int yb   = blockIdx.y;             // 0..2
    const int n0   = yb * 128;

    const unsigned smemBase = (unsigned)__cvta_generic_to_shared(smem);
    const int aRowL = wm * 64 + (lane & 15);
    const int aKoffL = (lane >> 4) << 4;
    const int bRow0 = wn * 16 + ((lane >> 4) << 3) + (lane & 7);
    const int bKoffL = ((lane >> 3) & 1) << 4;

    float acc[4][4][4];
#pragma unroll
    for (int i = 0; i < 4; i++)
#pragma unroll
        for (int j = 0; j < 4; j++)
#pragma unroll
            for (int k = 0; k < 4; k++) acc[i][j][k] = 0.f;

    auto load_stage = [&](int it, int s) {
        const int tap = it / CH;
        const int c0  = (it - tap * CH) * KB;
        const int dh = tap / 3 - 1;
        const int dw = tap % 3 - 1;
        const unsigned aB = smemBase + s * STGB;
        const unsigned bB = aB + ASTG;
        // A: 256 rows x CHK chunks = 512*(CHK/2) tasks
#pragma unroll
        for (int p = 0; p < CHK / 2; ++p) {
            const int task = tid + 512 * p;
            const int row = task / CHK;
            const int ch  = task - row * CHK;
            const int h = h0 + (row >> 5);
            const int w = row & 31;
            const int ih = h * STRIDE + dh;
            const int iw = w * STRIDE + dw;
            const bool ok = (ih >= 0) && (ih < HIN) && (iw >= 0) && (iw < HIN);
            const __half* src = ok
                ? inp + ((size_t)(bimg * HIN + ih) * HIN + iw) * CTOT + c0 + ch * 8
                : inp;
            cp_async16z(aB + (unsigned)(row * ROWB + ch * 16), src, ok ? 16 : 0);
        }
        // B: 128 rows x CHK chunks (packed source)
        const __half* wsrc = wp + (size_t)it * (384 * KB) + (size_t)n0 * KB;
#pragma unroll
        for (int p = 0; p < (128 * CHK + 511) / 512; ++p) {
            const int task = tid + 512 * p;
            if (task < 128 * CHK) {
                const int row = task / CHK;
                const int ch  = task - row * CHK;
                cp_async16(bB + (unsigned)(row * ROWB + ch * 16),
                           wsrc + row * KB + ch * 8);
            }
        }
    };

    // prologue: NST-1 stages in flight
#pragma unroll
    for (int ps = 0; ps < NST - 1; ++ps) {
        load_stage(ps, ps);
        asm volatile("cp.async.commit_group;\n" ::: "memory");
    }

    int s = 0;
#pragma unroll 1
    for (int it = 0; it < NIT; ++it) {
        int wgn = NIT - 1 - it;
        if (wgn > NST - 2) wgn = NST - 2;
        if (wgn <= 0)
            asm volatile("cp.async.wait_group 0;\n" ::: "memory");
        else if (wgn == 1)
            asm volatile("cp.async.wait_group 1;\n" ::: "memory");
        else
            asm volatile("cp.async.wait_group 2;\n" ::: "memory");
        __syncthreads();

        if (it + NST - 1 < NIT) {
            int sw = s - 1; if (sw < 0) sw += NST;   // == (it+NST-1) % NST
            load_stage(it + NST - 1, sw);
            asm volatile("cp.async.commit_group;\n" ::: "memory");
        }

        const unsigned aB = smemBase + s * STGB;
        const unsigned bB = aB + ASTG;
#pragma unroll
        for (int step = 0; step < KSTEPS; ++step) {
            const int kb = step * 32;
            uint32_t af[4][4];
#pragma unroll
            for (int mi = 0; mi < 4; ++mi)
                ldsm4(af[mi][0], af[mi][1], af[mi][2], af[mi][3],
                      aB + (unsigned)((aRowL + mi * 16) * ROWB + kb + aKoffL));
            uint32_t bf[4][2];
            ldsm4(bf[0][0], bf[0][1], bf[1][0], bf[1][1],
                  bB + (unsigned)(bRow0 * ROWB + kb + bKoffL));
            ldsm4(bf[2][0], bf[2][1], bf[3][0], bf[3][1],
                  bB + (unsigned)((bRow0 + 64) * ROWB + kb + bKoffL));
#pragma unroll
            for (int mi = 0; mi < 4; ++mi)
#pragma unroll
                for (int ni = 0; ni < 4; ++ni) {
                    asm volatile(
                        "mma.sync.aligned.m16n8k16.row.col.f32.f16.f16.f32 "
                        "{%0,%1,%2,%3}, {%4,%5,%6,%7}, {%8,%9}, {%0,%1,%2,%3};"
                        : "+f"(acc[mi][ni][0]), "+f"(acc[mi][ni][1]),
                          "+f"(acc[mi][ni][2]), "+f"(acc[mi][ni][3])
                        : "r"(af[mi][0]), "r"(af[mi][1]),
                          "r"(af[mi][2]), "r"(af[mi][3]),
                          "r"(bf[ni][0]), "r"(bf[ni][1]));
                }
        }
        if (++s == NST) s = 0;
    }

    // ---- fused affine epilogue -------------------------------------------
    // ni in {0,1}: lo channel c = yb*64 + wn*16 + ni*8 + 2*t4 (+0/1)
    // paired hi accumulator at ni+2 (channel c+192)
#pragma unroll
    for (int ni = 0; ni < 2; ++ni) {
        const int c = yb * 64 + wn * 16 + ni * 8 + 2 * t4;   // even
        const float bl0 = bias[c],        bl1 = bias[c + 1];
        const float bh0 = bias[c + 192],  bh1 = bias[c + 193];
        const int p0 = PBASE + c, p1 = PBASE + c + 1;
        const float sc0 = g_scale[p0], sc1 = g_scale[p1];
        const float ao0 = act_offset[p0], ao1 = act_offset[p1];
        const int o0 = g_invperm[p0], o1 = g_invperm[p1];
        const int cc = c >> 2, ii = (c >> 1) & 1;
        const float* xrowb = x + (((size_t)bimg * 96 + XOFF + cc) * 64 + ii) * 64;
#pragma unroll
        for (int mi = 0; mi < 4; ++mi) {
#pragma unroll
            for (int rr = 0; rr < 2; ++rr) {
                const int m = wm * 64 + mi * 16 + g4 + rr * 8;
                const int h = h0 + (m >> 5);
                const int w = m & 31;
                const float lo0 = acc[mi][ni][rr * 2 + 0] + bl0;
                const float lo1 = acc[mi][ni][rr * 2 + 1] + bl1;
                const float hi0 = acc[mi][ni + 2][rr * 2 + 0] + bh0;
                const float hi1 = acc[mi][ni + 2][rr * 2 + 1] + bh1;
                const float2 xd = *(const float2*)&xrowb[(size_t)(2 * h) * 64 + 2 * w];
                const float y0 = xd.x * expf(2.0f * tanhf(0.2f * lo0)) + hi0;
                const float y1 = xd.y * expf(2.0f * tanhf(0.2f * lo1)) + hi1;
                const int hw = h * 32 + w;
                if (WHICH == 1) {
                    *(__half2*)&g_y2h[(((size_t)(bimg * 32 + h) * 32) + w) * 192 + c] =
                        __floats2half2_rn(y0, y1);
                }
                outp[(((size_t)(bimg * 384 + o0)) << 10) + hw] = y0 * sc0 + ao0;
                outp[(((size_t)(bimg * 384 + o1)) << 10) + hw] = y1 * sc1 + ao1;
            }
        }
    }
}

// ---------------------------------------------------------------------------
extern "C" void kernel_launch(void* const* d_in, const int* in_sizes, int n_in,
                              void* d_out, int out_size) {
    const float* x          = (const float*)d_in[0];
    const float* w_hi       = (const float*)d_in[1];
    const float* b_hi       = (const float*)d_in[2];
    const float* w_lo       = (const float*)d_in[3];
    const float* b_lo       = (const float*)d_in[4];
    const float* act_norm   = (const float*)d_in[5];
    const float* act_offset = (const float*)d_in[6];
    const float* perm_w     = (const float*)d_in[7];
    float* out = (float*)d_out;

    // conv1: KB=48, NST=3 -> stage (256+128)*112 = 43,008 B, total 129,024 B
    // conv2: KB=64, NST=3 -> stage (256+128)*144 = 55,296 B, total 165,888 B
    const int SMEM1 = 3 * 384 * (48 * 2 + 16);
    const int SMEM2 = 3 * 384 * (64 * 2 + 16);

    cudaFuncSetAttribute(conv_fused<48, 3, 1, 2, 64, 48, 1>,
                         cudaFuncAttributeMaxDynamicSharedMemorySize, SMEM1);
    cudaFuncSetAttribute(conv_fused<64, 3, 3, 1, 32, 192, 2>,
                         cudaFuncAttributeMaxDynamicSharedMemorySize, SMEM2);

    prep_kernel<<<1, 384>>>(perm_w, act_norm);
    {
        int total = 9 * 384 * 48 + 27 * 384 * 64;
        pack_all_kernel<<<(total + 255) / 256, 256>>>(w_hi, w_lo);
    }
    x2h_kernel<<<32 * 64, 256>>>(x);

    conv_fused<48, 3, 1, 2, 64, 48, 1><<<dim3(128, 3), 512, SMEM1>>>(
        x, b_hi, act_offset, out);

    conv_fused<64, 3, 3, 1, 32, 192, 2><<<dim3(128, 3), 512, SMEM2>>>(
        x, b_lo, act_offset, out);
}

// round 16
// speedup vs baseline: 1.5297x; 1.1071x over previous
#include <cuda_runtime.h>
#include <cuda_fp16.h>
#include <math.h>
#include <stdint.h>

// ---------------------------------------------------------------------------
// AIO_DownsampleCouplingBlock — Round 16: round-11 base (best: 238.3us) +
// phase-split downsampled x1 so conv1's stride-2 A-gathers become unit-stride
// (halves conv1 L2 sector traffic).
// ---------------------------------------------------------------------------

__device__ __align__(16) __half g_xh[32 * 4 * 32 * 32 * 48];  // x1 phases [b][ph][h'][w'][48]
__device__ __align__(16) __half g_y2h[32 * 32 * 32 * 192];    // y2 NHWC half
__device__ __align__(16) __half g_wp1[9 * 384 * 48];          // conv1 w [tap][nn][48]
__device__ __align__(16) __half g_wp2[27 * 384 * 64];         // conv2 w [st][nn][64]
__device__ int   g_invperm[384];
__device__ float g_scale[384];

__device__ __forceinline__ void cp_async16(unsigned dst, const void* src) {
    asm volatile("cp.async.cg.shared.global [%0], [%1], 16;\n"
                 :: "r"(dst), "l"(src));
}
__device__ __forceinline__ void cp_async16z(unsigned dst, const void* src, int sz) {
    asm volatile("cp.async.cg.shared.global [%0], [%1], 16, %2;\n"
                 :: "r"(dst), "l"(src), "r"(sz));
}
__device__ __forceinline__ void ldsm4(uint32_t& r0, uint32_t& r1,
                                      uint32_t& r2, uint32_t& r3, unsigned addr) {
    asm volatile("ldmatrix.sync.aligned.m8n8.x4.shared.b16 {%0,%1,%2,%3}, [%4];"
                 : "=r"(r0), "=r"(r1), "=r"(r2), "=r"(r3) : "r"(addr));
}

// ---------------------------------------------------------------------------
__global__ void prep_kernel(const float* __restrict__ perm_w,
                            const float* __restrict__ act_norm) {
    int p = threadIdx.x;
    if (p < 384) {
        int o_found = 0;
        for (int o = 0; o < 384; ++o)
            if (perm_w[o * 384 + p] > 0.5f) o_found = o;
        g_invperm[p] = o_found;
        g_scale[p] = 0.2f * log1pf(expf(0.5f * act_norm[p]));
    }
}

// nn remap (128-col N-blocks): block y = nn>>7, r = nn&127:
//   r < 64 : n = y*64 + r ; r >= 64 : n = 192 + y*64 + (r-64)
__device__ __forceinline__ int nn_to_n(int nn) {
    int yb = nn >> 7, r = nn & 127;
    return (r < 64) ? (yb * 64 + r) : (192 + yb * 64 + (r - 64));
}

// both weight packs: dst[st][nn(384)][k(KB)], exact K (no pad)
__global__ void pack_all_kernel(const float* __restrict__ w_hi,
                                const float* __restrict__ w_lo) {
    const int T1 = 9 * 384 * 48;
    const int T2 = 27 * 384 * 64;
    int idx = blockIdx.x * 256 + threadIdx.x;
    if (idx < T1) {
        int k = idx % 48;
        int nn = (idx / 48) % 384;
        int tap = idx / (48 * 384);
        int n = nn_to_n(nn);
        g_wp1[idx] = __float2half(w_hi[(n * 48 + k) * 9 + tap]);
    } else if (idx < T1 + T2) {
        int j = idx - T1;
        int k = j % 64;
        int nn = (j / 64) % 384;
        int st = j / (64 * 384);          // tap = st/3, cblk = st%3
        int n = nn_to_n(nn);
        int tap = st / 3;
        int c = (st % 3) * 64 + k;
        g_wp2[j] = __float2half(w_lo[(n * 192 + c) * 9 + tap]);
    }
}

// x (NCHW f32, first 48 ch) -> g_xh phase-split [b][ph][h'][w'][48] half.
// block = (b, ih); phase ph = (ih&1)*2 + (iw&1); h'=ih>>1, w'=iw>>1.
__global__ __launch_bounds__(256) void x2h_kernel(const float* __restrict__ x) {
    __shared__ float tile[48][65];
    const int b = blockIdx.x >> 6, ih = blockIdx.x & 63;
    for (int idx = threadIdx.x; idx < 48 * 64; idx += 256) {
        const int c = idx >> 6, w = idx & 63;
        tile[c][w] = x[(((size_t)b * 96 + c) * 64 + ih) * 64 + w];
    }
    __syncthreads();
    const int ph_h = (ih & 1) << 1, hp = ih >> 1;
    for (int idx = threadIdx.x; idx < 64 * 24; idx += 256) {
        const int iw = idx / 24, cp = idx % 24;
        const int ph = ph_h | (iw & 1), wp = iw >> 1;
        __half2 v = __floats2half2_rn(tile[2 * cp][iw], tile[2 * cp + 1][iw]);
        *(__half2*)&g_xh[((((size_t)(b * 4 + ph)) * 32 + hp) * 32 + wp) * 48 + 2 * cp] = v;
    }
}

// ---------------------------------------------------------------------------
// fused implicit-GEMM conv + affine epilogue (round-11 structure).
// 256 thr / 8 warps, 2 CTAs/SM. Warp grid 2(M) x 4(N), warp tile 64x32.
// BM=128, BN=128 (64 lo + 64 paired hi). A/B smem rows padded +16B.
// conv1 (WHICH=1): A from phase-split g_xh, unit-stride rows.
// conv2 (WHICH=2): A from g_y2h NHWC, unit-stride rows.
// ---------------------------------------------------------------------------
template <int KB, int NST, int CH, int HIN, int CTOT, int WHICH>
__global__ __launch_bounds__(256, 2) void conv_fused(
    const float* __restrict__ x,
    const float* __restrict__ bias,
    const float* __restrict__ act_offset,
    float* __restrict__ outp) {
    extern __shared__ __align__(16) char smem[];

    constexpr int ROWB   = KB * 2 + 16;      // bytes per smem row
    constexpr int ASTG   = 128 * ROWB;
    constexpr int STGB   = 2 * ASTG;
    constexpr int KSTEPS = KB / 16;
    constexpr int CHK    = KB / 8;           // 16B chunks per row
    constexpr int TPT    = CHK / 2;          // A tasks per thread
    constexpr int NIT    = 9 * CH;

    const __half* inp = (WHICH == 1) ? (const __half*)g_xh : (const __half*)g_y2h;
    const __half* wp  = (WHICH == 1) ? (const __half*)g_wp1 : (const __half*)g_wp2;
    constexpr int XOFF  = (WHICH == 1) ? 48 : 0;
    constexpr int PBASE = (WHICH == 1) ? 192 : 0;

    const int tid  = threadIdx.x;
    const int lane = tid & 31;
    const int warp = tid >> 5;
    const int wm = warp >> 2;
    const int wn = warp & 3;
    const int g4 = lane >> 2;
    const int t4 = lane & 3;

    const int bm   = blockIdx.x;
    const int bimg = bm >> 3;
    const int h0   = (bm & 7) * 4;
    const int yb   = blockIdx.y;
    const int n0   = yb * 128;

    const unsigned smemBase = (unsigned)__cvta_generic_to_shared(smem);
    const int aRowL = wm * 64 + (lane & 15);
    const int aKoffL = (lane >> 4) << 4;
    const int bRow0 = wn * 16 + ((lane >> 4) << 3) + (lane & 7);
    const int bKoffL = ((lane >> 3) & 1) << 4;

    float acc[4][4][4];
#pragma unroll
    for (int i = 0; i < 4; i++)
#pragma unroll
        for (int j = 0; j < 4; j++)
#pragma unroll
            for (int k = 0; k < 4; k++) acc[i][j][k] = 0.f;

    auto load_stage = [&](int it, int s) {
        const int tap = it / CH;
        const int c0  = (it - tap * CH) * KB;
        const int dh = tap / 3 - 1;
        const int dw = tap % 3 - 1;
        const unsigned aB = smemBase + s * STGB;
        const unsigned bB = aB + ASTG;
        if (WHICH == 1) {
            // phase-split: ph = parity(dh,dw); offsets -1 only for the -1 taps
            const int ph   = ((dh & 1) << 1) | (dw & 1);
            const int hoff = dh >> 1;        // -1 -> -1, 0/1 -> 0
            const int woff = dw >> 1;
            const __half* base = inp + ((size_t)(bimg * 4 + ph) * 32) * 32 * 48;
#pragma unroll
            for (int p = 0; p < TPT; ++p) {
                const int task = tid + 256 * p;
                const int row = task / CHK;
                const int ch  = task - row * CHK;
                const int hp = h0 + (row >> 5) + hoff;
                const int wpx = (row & 31) + woff;
                const bool ok = (hp >= 0) && (wpx >= 0);
                const __half* src = ok
                    ? base + ((size_t)hp * 32 + wpx) * 48 + ch * 8
                    : inp;
                cp_async16z(aB + (unsigned)(row * ROWB + ch * 16), src, ok ? 16 : 0);
            }
        } else {
#pragma unroll
            for (int p = 0; p < TPT; ++p) {
                const int task = tid + 256 * p;
                const int row = task / CHK;
                const int ch  = task - row * CHK;
                const int h = h0 + (row >> 5);
                const int w = row & 31;
                const int ih = h + dh;
                const int iw = w + dw;
                const bool ok = (ih >= 0) && (ih < HIN) && (iw >= 0) && (iw < HIN);
                const __half* src = ok
                    ? inp + ((size_t)(bimg * HIN + ih) * HIN + iw) * CTOT + c0 + ch * 8
                    : inp;
                cp_async16z(aB + (unsigned)(row * ROWB + ch * 16), src, ok ? 16 : 0);
            }
        }
        const __half* wsrc = wp + (size_t)it * (384 * KB) + (size_t)n0 * KB;
#pragma unroll
        for (int p = 0; p < TPT; ++p) {
            const int task = tid + 256 * p;
            const int row = task / CHK;
            const int ch  = task - row * CHK;
            cp_async16(bB + (unsigned)(row * ROWB + ch * 16), wsrc + row * KB + ch * 8);
        }
    };

    // prologue: NST-1 stages in flight
#pragma unroll
    for (int ps = 0; ps < NST - 1; ++ps) {
        load_stage(ps, ps);
        asm volatile("cp.async.commit_group;\n" ::: "memory");
    }

    int s = 0;
#pragma unroll 1
    for (int it = 0; it < NIT; ++it) {
        int wgn = NIT - 1 - it;
        if (wgn > NST - 2) wgn = NST - 2;
        if (wgn <= 0)
            asm volatile("cp.async.wait_group 0;\n" ::: "memory");
        else if (wgn == 1)
            asm volatile("cp.async.wait_group 1;\n" ::: "memory");
        else
            asm volatile("cp.async.wait_group 2;\n" ::: "memory");
        __syncthreads();

        if (it + NST - 1 < NIT) {
            int sw = s - 1; if (sw < 0) sw += NST;   // == (it+NST-1) % NST
            load_stage(it + NST - 1, sw);
            asm volatile("cp.async.commit_group;\n" ::: "memory");
        }

        const unsigned aB = smemBase + s * STGB;
        const unsigned bB = aB + ASTG;
#pragma unroll
        for (int step = 0; step < KSTEPS; ++step) {
            const int kb = step * 32;
            uint32_t af[4][4];
#pragma unroll
            for (int mi = 0; mi < 4; ++mi)
                ldsm4(af[mi][0], af[mi][1], af[mi][2], af[mi][3],
                      aB + (unsigned)((aRowL + mi * 16) * ROWB + kb + aKoffL));
            uint32_t bf[4][2];
            ldsm4(bf[0][0], bf[0][1], bf[1][0], bf[1][1],
                  bB + (unsigned)(bRow0 * ROWB + kb + bKoffL));
            ldsm4(bf[2][0], bf[2][1], bf[3][0], bf[3][1],
                  bB + (unsigned)((bRow0 + 64) * ROWB + kb + bKoffL));
#pragma unroll
            for (int mi = 0; mi < 4; ++mi)
#pragma unroll
                for (int ni = 0; ni < 4; ++ni) {
                    asm volatile(
                        "mma.sync.aligned.m16n8k16.row.col.f32.f16.f16.f32 "
                        "{%0,%1,%2,%3}, {%4,%5,%6,%7}, {%8,%9}, {%0,%1,%2,%3};"
                        : "+f"(acc[mi][ni][0]), "+f"(acc[mi][ni][1]),
                          "+f"(acc[mi][ni][2]), "+f"(acc[mi][ni][3])
                        : "r"(af[mi][0]), "r"(af[mi][1]),
                          "r"(af[mi][2]), "r"(af[mi][3]),
                          "r"(bf[ni][0]), "r"(bf[ni][1]));
                }
        }
        if (++s == NST) s = 0;
    }

    // ---- fused affine epilogue -------------------------------------------
    // ni in {0,1}: lo channel c = yb*64 + wn*16 + ni*8 + 2*t4 (+0/1)
    // paired hi accumulator at ni+2 (channel c+192)
#pragma unroll
    for (int ni = 0; ni < 2; ++ni) {
        const int c = yb * 64 + wn * 16 + ni * 8 + 2 * t4;   // even
        const float bl0 = bias[c],        bl1 = bias[c + 1];
        const float bh0 = bias[c + 192],  bh1 = bias[c + 193];
        const int p0 = PBASE + c, p1 = PBASE + c + 1;
        const float sc0 = g_scale[p0], sc1 = g_scale[p1];
        const float ao0 = act_offset[p0], ao1 = act_offset[p1];
        const int o0 = g_invperm[p0], o1 = g_invperm[p1];
        const int cc = c >> 2, ii = (c >> 1) & 1;
        const float* xrowb = x + (((size_t)bimg * 96 + XOFF + cc) * 64 + ii) * 64;
#pragma unroll
        for (int mi = 0; mi < 4; ++mi) {
#pragma unroll
            for (int rr = 0; rr < 2; ++rr) {
                const int m = wm * 64 + mi * 16 + g4 + rr * 8;
                const int h = h0 + (m >> 5);
                const int w = m & 31;
                const float lo0 = acc[mi][ni][rr * 2 + 0] + bl0;
                const float lo1 = acc[mi][ni][rr * 2 + 1] + bl1;
                const float hi0 = acc[mi][ni + 2][rr * 2 + 0] + bh0;
                const float hi1 = acc[mi][ni + 2][rr * 2 + 1] + bh1;
                const float2 xd = *(const float2*)&xrowb[(size_t)(2 * h) * 64 + 2 * w];
                const float y0 = xd.x * expf(2.0f * tanhf(0.2f * lo0)) + hi0;
                const float y1 = xd.y * expf(2.0f * tanhf(0.2f * lo1)) + hi1;
                const int hw = h * 32 + w;
                if (WHICH == 1) {
                    *(__half2*)&g_y2h[(((size_t)(bimg * 32 + h) * 32) + w) * 192 + c] =
                        __floats2half2_rn(y0, y1);
                }
                outp[(((size_t)(bimg * 384 + o0)) << 10) + hw] = y0 * sc0 + ao0;
                outp[(((size_t)(bimg * 384 + o1)) << 10) + hw] = y1 * sc1 + ao1;
            }
        }
    }
}

// ---------------------------------------------------------------------------
extern "C" void kernel_launch(void* const* d_in, const int* in_sizes, int n_in,
                              void* d_out, int out_size) {
    const float* x          = (const float*)d_in[0];
    const float* w_hi       = (const float*)d_in[1];
    const float* b_hi       = (const float*)d_in[2];
    const float* w_lo       = (const float*)d_in[3];
    const float* b_lo       = (const float*)d_in[4];
    const float* act_norm   = (const float*)d_in[5];
    const float* act_offset = (const float*)d_in[6];
    const float* perm_w     = (const float*)d_in[7];
    float* out = (float*)d_out;

    // conv1: KB=48, NST=4 -> stage 28,672 B, total 114,688 B  (2 CTAs/SM)
    // conv2: KB=64, NST=3 -> stage 36,864 B, total 110,592 B  (2 CTAs/SM)
    const int SMEM1 = 4 * 2 * 128 * (48 * 2 + 16);
    const int SMEM2 = 3 * 2 * 128 * (64 * 2 + 16);

    cudaFuncSetAttribute(conv_fused<48, 4, 1, 32, 48, 1>,
                         cudaFuncAttributeMaxDynamicSharedMemorySize, SMEM1);
    cudaFuncSetAttribute(conv_fused<64, 3, 3, 32, 192, 2>,
                         cudaFuncAttributeMaxDynamicSharedMemorySize, SMEM2);

    prep_kernel<<<1, 384>>>(perm_w, act_norm);
    {
        int total = 9 * 384 * 48 + 27 * 384 * 64;
        pack_all_kernel<<<(total + 255) / 256, 256>>>(w_hi, w_lo);
    }
    x2h_kernel<<<32 * 64, 256>>>(x);

    conv_fused<48, 4, 1, 32, 48, 1><<<dim3(256, 3), 256, SMEM1>>>(
        x, b_hi, act_offset, out);

    conv_fused<64, 3, 3, 32, 192, 2><<<dim3(256, 3), 256, SMEM2>>>(
        x, b_lo, act_offset, out);
}